// round 9
// baseline (speedup 1.0000x reference)
#include <cuda_runtime.h>

#define BB   4
#define TT   12
#define FIN  8
#define HID  32
#define KORD 3
#define NMAX 50048
#define EMAX 2000128
#define FULLM 0xffffffffu

// ---------------- scratch (device globals; no runtime allocation) ----------------
__device__ float  g_deg[NMAX];
__device__ float  g_dinv[NMAX];
__device__ float  g_diag[NMAX];
__device__ int    g_row[EMAX];
__device__ int    g_col[EMAX];
__device__ int    g_cnt[NMAX];
__device__ int    g_cur[NMAX];
__device__ int    g_off[NMAX + 1];
__device__ float2 g_edge[EMAX];                 // (bitcast src, norm weight)
__device__ int    g_idx64;
__device__ float  g_X  [NMAX * FIN * BB];       // [n][f][b]
__device__ float  g_T1 [NMAX * HID * BB];
__device__ float  g_T2 [NMAX * HID * BB];
__device__ float  g_T1b[NMAX * HID * BB];       // persisted basis(H1) hop 1
__device__ float  g_T2b[NMAX * HID * BB];       // persisted basis(H1) hop 2
__device__ float  g_gx [NMAX * 3 * HID * BB];   // [n][g][o][b]
__device__ float  g_H1 [NMAX * HID * BB];
__device__ float  g_H2 [NMAX * HID * BB];
__device__ float  g_Zb [NMAX * HID * BB];
__device__ float  g_HR [NMAX * HID * BB];
__device__ float  g_S  [HID * BB];

__device__ __forceinline__ float sigm(float x) { return 1.f / (1.f + expf(-x)); }
__device__ __forceinline__ float softplusf(float x) {
    return (x > 20.f) ? x : log1pf(expf(x));
}

// ---------------- setup kernels ----------------
__global__ void detect_k(const int* __restrict__ ei32, int n_words) {
    int allzero = 1;
    int lim = n_words < 256 ? n_words : 256;
    for (int i = 1; i < lim; i += 2)
        if (ei32[i] != 0) { allzero = 0; break; }
    g_idx64 = allzero;
}

__global__ void edge_init_k(const void* __restrict__ ei,
                            const float* __restrict__ ew, int E) {
    int e = blockIdx.x * blockDim.x + threadIdx.x;
    if (e >= E) return;
    int r, c;
    if (g_idx64) {
        const long long* p = (const long long*)ei;
        r = (int)p[e];
        c = (int)p[E + e];
    } else {
        const int* p = (const int*)ei;
        r = p[e];
        c = p[E + e];
    }
    g_row[e] = r;
    g_col[e] = c;
    atomicAdd(&g_deg[r], ew[e]);
    atomicAdd(&g_cnt[c], 1);
}

__global__ void node_prep_k(int N_) {
    int n = blockIdx.x * blockDim.x + threadIdx.x;
    if (n >= N_) return;
    float d = g_deg[n];
    if (d > 0.f) { g_dinv[n] = rsqrtf(d); g_diag[n] = 0.f; }
    else         { g_dinv[n] = 0.f;       g_diag[n] = -1.f; }
}

__global__ void scan_k(int N_) {
    __shared__ int part[1024];
    int tid = threadIdx.x;
    int chunk = (N_ + 1023) / 1024;
    int start = tid * chunk;
    int end = min(start + chunk, N_);
    if (end < start) end = start;
    int sum = 0;
    for (int i = start; i < end; i++) sum += g_cnt[i];
    part[tid] = sum;
    __syncthreads();
    for (int off = 1; off < 1024; off <<= 1) {
        int v = (tid >= off) ? part[tid - off] : 0;
        __syncthreads();
        part[tid] += v;
        __syncthreads();
    }
    int excl = part[tid] - sum;
    int run = excl;
    for (int i = start; i < end; i++) { g_off[i] = run; run += g_cnt[i]; }
    if (tid == 1023) g_off[N_] = part[1023];
}

__global__ void fill_k(const float* __restrict__ ew, int E) {
    int e = blockIdx.x * blockDim.x + threadIdx.x;
    if (e >= E) return;
    int r = g_row[e], c = g_col[e];
    int pos = g_off[c] + atomicAdd(&g_cur[c], 1);
    g_edge[pos] = make_float2(__int_as_float(r), -ew[e] * g_dinv[r] * g_dinv[c]);
}

__global__ void xgather_k(const float* __restrict__ in, int t, int N_) {
    int tid = blockIdx.x * blockDim.x + threadIdx.x;
    if (tid >= N_ * FIN * BB) return;
    int b = tid / (N_ * FIN);
    int rem = tid - b * (N_ * FIN);
    int n = rem / FIN;
    int f = rem - n * FIN;
    g_X[(n * FIN + f) * BB + b] = in[(((long long)b * TT + t) * N_ + n) * FIN + f];
}

__global__ void zero2_k(float* __restrict__ a, float* __restrict__ b, int nfloat4) {
    int i = blockIdx.x * blockDim.x + threadIdx.x;
    if (i >= nfloat4) return;
    ((float4*)a)[i] = make_float4(0.f, 0.f, 0.f, 0.f);
    ((float4*)b)[i] = make_float4(0.f, 0.f, 0.f, 0.f);
}

// ---------------- SpMM ----------------
template <int FB, bool CHEB>
__global__ void spmm_k(float* __restrict__ out, const float* __restrict__ x,
                       const float* __restrict__ t0, int N_) {
    int gw = (blockIdx.x * blockDim.x + threadIdx.x) >> 5;
    int lane = threadIdx.x & 31;
    if (gw >= N_) return;
    int o0 = g_off[gw], o1 = g_off[gw + 1];
    if constexpr (FB == 128) {
        const float4* x4 = (const float4*)x;
        float4 acc = make_float4(0.f, 0.f, 0.f, 0.f);
        for (int base = o0; base < o1; base += 32) {
            int idx = base + lane;
            int s = 0; float w = 0.f;
            if (idx < o1) {
                float2 e = g_edge[idx];
                s = __float_as_int(e.x); w = e.y;
            }
            int m = min(32, o1 - base);
            int j = 0;
            for (; j + 3 < m; j += 4) {
                int   s0 = __shfl_sync(FULLM, s, j);
                int   s1 = __shfl_sync(FULLM, s, j + 1);
                int   s2 = __shfl_sync(FULLM, s, j + 2);
                int   s3 = __shfl_sync(FULLM, s, j + 3);
                float w0 = __shfl_sync(FULLM, w, j);
                float w1 = __shfl_sync(FULLM, w, j + 1);
                float w2 = __shfl_sync(FULLM, w, j + 2);
                float w3 = __shfl_sync(FULLM, w, j + 3);
                float4 v0 = x4[s0 * 32 + lane];
                float4 v1 = x4[s1 * 32 + lane];
                float4 v2 = x4[s2 * 32 + lane];
                float4 v3 = x4[s3 * 32 + lane];
                acc.x = fmaf(w0, v0.x, acc.x); acc.y = fmaf(w0, v0.y, acc.y);
                acc.z = fmaf(w0, v0.z, acc.z); acc.w = fmaf(w0, v0.w, acc.w);
                acc.x = fmaf(w1, v1.x, acc.x); acc.y = fmaf(w1, v1.y, acc.y);
                acc.z = fmaf(w1, v1.z, acc.z); acc.w = fmaf(w1, v1.w, acc.w);
                acc.x = fmaf(w2, v2.x, acc.x); acc.y = fmaf(w2, v2.y, acc.y);
                acc.z = fmaf(w2, v2.z, acc.z); acc.w = fmaf(w2, v2.w, acc.w);
                acc.x = fmaf(w3, v3.x, acc.x); acc.y = fmaf(w3, v3.y, acc.y);
                acc.z = fmaf(w3, v3.z, acc.z); acc.w = fmaf(w3, v3.w, acc.w);
            }
            for (; j < m; j++) {
                int   sj = __shfl_sync(FULLM, s, j);
                float wj = __shfl_sync(FULLM, w, j);
                float4 v = x4[sj * 32 + lane];
                acc.x = fmaf(wj, v.x, acc.x); acc.y = fmaf(wj, v.y, acc.y);
                acc.z = fmaf(wj, v.z, acc.z); acc.w = fmaf(wj, v.w, acc.w);
            }
        }
        float dg = g_diag[gw];
        float4 xv = x4[gw * 32 + lane];
        acc.x = fmaf(dg, xv.x, acc.x); acc.y = fmaf(dg, xv.y, acc.y);
        acc.z = fmaf(dg, xv.z, acc.z); acc.w = fmaf(dg, xv.w, acc.w);
        if (CHEB) {
            float4 p = ((const float4*)t0)[gw * 32 + lane];
            acc.x = 2.f * acc.x - p.x; acc.y = 2.f * acc.y - p.y;
            acc.z = 2.f * acc.z - p.z; acc.w = 2.f * acc.w - p.w;
        }
        ((float4*)out)[gw * 32 + lane] = acc;
    } else {  // FB == 32 (F=8, B=4)
        float acc = 0.f;
        for (int base = o0; base < o1; base += 32) {
            int idx = base + lane;
            int s = 0; float w = 0.f;
            if (idx < o1) {
                float2 e = g_edge[idx];
                s = __float_as_int(e.x); w = e.y;
            }
            int m = min(32, o1 - base);
            int j = 0;
            for (; j + 3 < m; j += 4) {
                int   s0 = __shfl_sync(FULLM, s, j);
                int   s1 = __shfl_sync(FULLM, s, j + 1);
                int   s2 = __shfl_sync(FULLM, s, j + 2);
                int   s3 = __shfl_sync(FULLM, s, j + 3);
                float w0 = __shfl_sync(FULLM, w, j);
                float w1 = __shfl_sync(FULLM, w, j + 1);
                float w2 = __shfl_sync(FULLM, w, j + 2);
                float w3 = __shfl_sync(FULLM, w, j + 3);
                float v0 = x[s0 * 32 + lane];
                float v1 = x[s1 * 32 + lane];
                float v2 = x[s2 * 32 + lane];
                float v3 = x[s3 * 32 + lane];
                acc = fmaf(w0, v0, acc);
                acc = fmaf(w1, v1, acc);
                acc = fmaf(w2, v2, acc);
                acc = fmaf(w3, v3, acc);
            }
            for (; j < m; j++) {
                int   sj = __shfl_sync(FULLM, s, j);
                float wj = __shfl_sync(FULLM, w, j);
                acc = fmaf(wj, x[sj * 32 + lane], acc);
            }
        }
        acc = fmaf(g_diag[gw], x[gw * 32 + lane], acc);
        if (CHEB) acc = 2.f * acc - t0[gw * 32 + lane];
        out[gw * 32 + lane] = acc;
    }
}

// ---------------- gate kernels (grid-stride; weights loaded once per block) ----------------
template <int F>
__global__ void gx_k(const float* __restrict__ T0, const float* __restrict__ T1v,
                     const float* __restrict__ T2v, const float* __restrict__ Wx,
                     const float* __restrict__ bx, int N_) {
    constexpr int KF = KORD * F;
    extern __shared__ float sm[];
    float* wsh = sm;
    float* insh = sm + 3 * KF * 32;
    int tid = threadIdx.x;
    for (int i = tid; i < 3 * KF * 32; i += blockDim.x) wsh[i] = Wx[i];
    __syncthreads();
    int wid = tid >> 5, lane = tid & 31;
    float4* in4 = ((float4*)insh) + wid * KF;
    const float* Ts[3] = {T0, T1v, T2v};
    for (int n0 = blockIdx.x * 8; n0 < N_; n0 += gridDim.x * 8) {
        int n = n0 + wid;
        if (n >= N_) break;
        for (int k = 0; k < 3; k++)
            for (int i = lane; i < F; i += 32)
                in4[k * F + i] = ((const float4*)Ts[k])[n * F + i];
        __syncwarp();
        for (int g = 0; g < 3; g++) {
            float ax = 0.f, ay = 0.f, az = 0.f, aw = 0.f;
            const float* wg = wsh + g * KF * 32 + lane;
#pragma unroll 4
            for (int i = 0; i < KF; i++) {
                float w = wg[i * 32];
                float4 v = in4[i];
                ax = fmaf(w, v.x, ax); ay = fmaf(w, v.y, ay);
                az = fmaf(w, v.z, az); aw = fmaf(w, v.w, aw);
            }
            float bb = bx[g * 32 + lane];
            ((float4*)g_gx)[(n * 3 + g) * 32 + lane] =
                make_float4(ax + bb, ay + bb, az + bb, aw + bb);
        }
        __syncwarp();
    }
}

__global__ void zr_k(const float* __restrict__ T0, const float* __restrict__ T1v,
                     const float* __restrict__ T2v, const float* __restrict__ Wh,
                     const float* __restrict__ bh, int N_) {
    constexpr int F = HID, KF = KORD * HID;
    extern __shared__ float sm[];
    float* wsh = sm;
    float* insh = sm + 2 * KF * 32;
    int tid = threadIdx.x;
    for (int i = tid; i < 2 * KF * 32; i += blockDim.x) wsh[i] = Wh[i];
    __syncthreads();
    int wid = tid >> 5, lane = tid & 31;
    float4* in4 = ((float4*)insh) + wid * KF;
    const float* Ts[3] = {T0, T1v, T2v};
    for (int n0 = blockIdx.x * 8; n0 < N_; n0 += gridDim.x * 8) {
        int n = n0 + wid;
        if (n >= N_) break;
        for (int k = 0; k < 3; k++)
            for (int i = lane; i < F; i += 32)
                in4[k * F + i] = ((const float4*)Ts[k])[n * F + i];
        __syncwarp();
        float4 az = make_float4(0.f, 0.f, 0.f, 0.f);
        float4 ar = make_float4(0.f, 0.f, 0.f, 0.f);
        const float* wz = wsh + lane;
        const float* wr = wsh + KF * 32 + lane;
#pragma unroll 4
        for (int i = 0; i < KF; i++) {
            float4 v = in4[i];
            float a = wz[i * 32];
            az.x = fmaf(a, v.x, az.x); az.y = fmaf(a, v.y, az.y);
            az.z = fmaf(a, v.z, az.z); az.w = fmaf(a, v.w, az.w);
            float b = wr[i * 32];
            ar.x = fmaf(b, v.x, ar.x); ar.y = fmaf(b, v.y, ar.y);
            ar.z = fmaf(b, v.z, ar.z); ar.w = fmaf(b, v.w, ar.w);
        }
        float4 gx0 = ((const float4*)g_gx)[(n * 3 + 0) * 32 + lane];
        float4 gx1 = ((const float4*)g_gx)[(n * 3 + 1) * 32 + lane];
        float bz = bh[lane], br = bh[32 + lane];
        float4 H = in4[lane];
        float4 Z, HR;
        Z.x = sigm(gx0.x + az.x + bz); Z.y = sigm(gx0.y + az.y + bz);
        Z.z = sigm(gx0.z + az.z + bz); Z.w = sigm(gx0.w + az.w + bz);
        HR.x = H.x * sigm(gx1.x + ar.x + br);
        HR.y = H.y * sigm(gx1.y + ar.y + br);
        HR.z = H.z * sigm(gx1.z + ar.z + br);
        HR.w = H.w * sigm(gx1.w + ar.w + br);
        ((float4*)g_Zb)[n * 32 + lane] = Z;
        ((float4*)g_HR)[n * 32 + lane] = HR;
        __syncwarp();
    }
}

__global__ void gh_k(const float* __restrict__ T0, const float* __restrict__ T1v,
                     const float* __restrict__ T2v, const float* __restrict__ Wh2,
                     const float* __restrict__ bh2, float* __restrict__ Hio, int N_) {
    constexpr int F = HID, KF = KORD * HID;
    extern __shared__ float sm[];
    float* wsh = sm;
    float* insh = sm + KF * 32;
    int tid = threadIdx.x;
    for (int i = tid; i < KF * 32; i += blockDim.x) wsh[i] = Wh2[i];
    __syncthreads();
    int wid = tid >> 5, lane = tid & 31;
    float4* in4 = ((float4*)insh) + wid * KF;
    const float* Ts[3] = {T0, T1v, T2v};
    for (int n0 = blockIdx.x * 8; n0 < N_; n0 += gridDim.x * 8) {
        int n = n0 + wid;
        if (n >= N_) break;
        for (int k = 0; k < 3; k++)
            for (int i = lane; i < F; i += 32)
                in4[k * F + i] = ((const float4*)Ts[k])[n * F + i];
        __syncwarp();
        float4 ah = make_float4(0.f, 0.f, 0.f, 0.f);
        const float* wg = wsh + lane;
#pragma unroll 4
        for (int i = 0; i < KF; i++) {
            float4 v = in4[i];
            float a = wg[i * 32];
            ah.x = fmaf(a, v.x, ah.x); ah.y = fmaf(a, v.y, ah.y);
            ah.z = fmaf(a, v.z, ah.z); ah.w = fmaf(a, v.w, ah.w);
        }
        float4 gx2 = ((const float4*)g_gx)[(n * 3 + 2) * 32 + lane];
        float b2 = bh2[lane];
        float4 Z = ((const float4*)g_Zb)[n * 32 + lane];
        float4 H = ((const float4*)Hio)[n * 32 + lane];
        float4 Hn;
        Hn.x = Z.x * H.x + (1.f - Z.x) * tanhf(gx2.x + ah.x + b2);
        Hn.y = Z.y * H.y + (1.f - Z.y) * tanhf(gx2.y + ah.y + b2);
        Hn.z = Z.z * H.z + (1.f - Z.z) * tanhf(gx2.z + ah.z + b2);
        Hn.w = Z.w * H.w + (1.f - Z.w) * tanhf(gx2.w + ah.w + b2);
        ((float4*)Hio)[n * 32 + lane] = Hn;
        __syncwarp();
    }
}

// ---------------- heads ----------------
__global__ void musig_k(const float* __restrict__ H2, const float* __restrict__ muW,
                        const float* __restrict__ mub, const float* __restrict__ sgW,
                        const float* __restrict__ sgb, float* __restrict__ out, int N_) {
    int tid = blockIdx.x * blockDim.x + threadIdx.x;
    if (tid >= N_ * BB) return;
    int b = tid & 3;
    int n = tid >> 2;
    float a0 = 0.f, a1 = 0.f, s0 = 0.f, s1 = 0.f;
#pragma unroll
    for (int i = 0; i < HID; i++) {
        float h = H2[(n * HID + i) * BB + b];
        a0 = fmaf(h, muW[i * 2 + 0], a0);
        a1 = fmaf(h, muW[i * 2 + 1], a1);
        s0 = fmaf(h, sgW[i * 2 + 0], s0);
        s1 = fmaf(h, sgW[i * 2 + 1], s1);
    }
    a0 += mub[0]; a1 += mub[1]; s0 += sgb[0]; s1 += sgb[1];
    out[((long long)b * N_ + n) * 2 + 0] = sigm(a0);
    out[((long long)b * N_ + n) * 2 + 1] = sigm(a1);
    float* so = out + (long long)BB * N_ * 2;
    so[((long long)b * N_ + n) * 2 + 0] = softplusf(s0);
    so[((long long)b * N_ + n) * 2 + 1] = softplusf(s1);
}

__global__ void sum_k(const float* __restrict__ H2, int N_) {
    int tid = threadIdx.x;
    int per = (N_ + gridDim.x - 1) / gridDim.x;
    int n0 = blockIdx.x * per;
    int n1 = min(n0 + per, N_);
    float acc = 0.f;
    for (int n = n0; n < n1; n++) acc += H2[n * 128 + tid];
    atomicAdd(&g_S[tid], acc);
}

__global__ void mix_k(float* __restrict__ out, int N_) {
    int lane = threadIdx.x & 31;
    int b = threadIdx.x >> 5;
    float v = g_S[lane * BB + b] / (float)N_;
    float m = v;
    for (int o = 16; o; o >>= 1) m = fmaxf(m, __shfl_xor_sync(FULLM, m, o));
    float e = expf(v - m);
    float s = e;
    for (int o = 16; o; o >>= 1) s += __shfl_xor_sync(FULLM, s, o);
    out[(long long)BB * N_ * 4 + b * HID + lane] = e / s;
}

// ---------------- launcher ----------------
extern "C" void kernel_launch(void* const* d_in, const int* in_sizes, int n_in,
                              void* d_out, int out_size) {
    const float* in_tensor = (const float*)d_in[0];
    const void*  ei  = d_in[1];
    const float* ew  = (const float*)d_in[2];
    const float* Wx0 = (const float*)d_in[3];
    const float* Wh0 = (const float*)d_in[4];
    const float* bx0 = (const float*)d_in[5];
    const float* bh0 = (const float*)d_in[6];
    const float* Wx1 = (const float*)d_in[7];
    const float* Wh1 = (const float*)d_in[8];
    const float* bx1 = (const float*)d_in[9];
    const float* bh1 = (const float*)d_in[10];
    const float* muW = (const float*)d_in[11];
    const float* mub = (const float*)d_in[12];
    const float* sgW = (const float*)d_in[13];
    const float* sgb = (const float*)d_in[14];
    float* out = (float*)d_out;

    int E  = in_sizes[1] / 2;
    int N_ = in_sizes[0] / (BB * TT * FIN);

    void *pdeg, *pcnt, *pcur, *pS, *pH1, *pH2, *pT1, *pT2, *pT1b, *pT2b, *pX, *pHR;
    cudaGetSymbolAddress(&pdeg, g_deg);
    cudaGetSymbolAddress(&pcnt, g_cnt);
    cudaGetSymbolAddress(&pcur, g_cur);
    cudaGetSymbolAddress(&pS,   g_S);
    cudaGetSymbolAddress(&pH1,  g_H1);
    cudaGetSymbolAddress(&pH2,  g_H2);
    cudaGetSymbolAddress(&pT1,  g_T1);
    cudaGetSymbolAddress(&pT2,  g_T2);
    cudaGetSymbolAddress(&pT1b, g_T1b);
    cudaGetSymbolAddress(&pT2b, g_T2b);
    cudaGetSymbolAddress(&pX,   g_X);
    cudaGetSymbolAddress(&pHR,  g_HR);
    float *T1 = (float*)pT1, *T2 = (float*)pT2, *X = (float*)pX;
    float *T1b = (float*)pT1b, *T2b = (float*)pT2b;
    float *H1 = (float*)pH1, *H2 = (float*)pH2, *HR = (float*)pHR;

    const int smem_gx8  = (3 * KORD * FIN * 32 + 8 * KORD * FIN * 4) * 4;
    const int smem_gx32 = (3 * KORD * HID * 32 + 8 * KORD * HID * 4) * 4;
    const int smem_zr   = (2 * KORD * HID * 32 + 8 * KORD * HID * 4) * 4;
    const int smem_gh   = (1 * KORD * HID * 32 + 8 * KORD * HID * 4) * 4;
    cudaFuncSetAttribute((const void*)gx_k<FIN>, cudaFuncAttributeMaxDynamicSharedMemorySize, 65536);
    cudaFuncSetAttribute((const void*)gx_k<HID>, cudaFuncAttributeMaxDynamicSharedMemorySize, 65536);
    cudaFuncSetAttribute((const void*)zr_k,      cudaFuncAttributeMaxDynamicSharedMemorySize, 65536);
    cudaFuncSetAttribute((const void*)gh_k,      cudaFuncAttributeMaxDynamicSharedMemorySize, 65536);

    cudaMemsetAsync(pdeg, 0, (size_t)N_ * 4);
    cudaMemsetAsync(pcnt, 0, (size_t)N_ * 4);
    cudaMemsetAsync(pcur, 0, (size_t)N_ * 4);
    cudaMemsetAsync(pS,   0, 128 * 4);
    cudaMemsetAsync(pH1,  0, (size_t)N_ * 128 * 4);
    cudaMemsetAsync(pH2,  0, (size_t)N_ * 128 * 4);
    cudaMemsetAsync(pT1b, 0, (size_t)N_ * 128 * 4);
    cudaMemsetAsync(pT2b, 0, (size_t)N_ * 128 * 4);

    int ebl = (E + 255) / 256;
    int nb_sp = (N_ * 32 + 255) / 256;   // one warp per node
    int nb_g  = 592;
    int nzf   = (N_ * 32 + 255) / 256;
    const int WH = 2 * KORD * HID * HID;

    detect_k<<<1, 1>>>((const int*)ei, in_sizes[1]);
    edge_init_k<<<ebl, 256>>>(ei, ew, E);
    node_prep_k<<<(N_ + 255) / 256, 256>>>(N_);
    scan_k<<<1, 1024>>>(N_);
    fill_k<<<ebl, 256>>>(ew, E);

    for (int t = 0; t < TT; t++) {
        // ---- layer 0 (input F=8) ----
        xgather_k<<<(N_ * FIN * BB + 255) / 256, 256>>>(in_tensor, t, N_);
        spmm_k<32, false><<<nb_sp, 256>>>(T1, X, nullptr, N_);
        spmm_k<32, true ><<<nb_sp, 256>>>(T2, T1, X, N_);
        gx_k<FIN><<<nb_g, 256, smem_gx8>>>(X, T1, T2, Wx0, bx0, N_);
        // basis(H1) reused from layer 1 of prev step (zeroed at setup for t=0)
        zr_k<<<nb_g, 256, smem_zr>>>(H1, T1b, T2b, Wh0, bh0, N_);
        if (t == 0) {
            zero2_k<<<nzf, 256>>>(T1, T2, N_ * 32);     // basis(HR)==0 at t=0
        } else {
            spmm_k<128, false><<<nb_sp, 256>>>(T1, HR, nullptr, N_);
            spmm_k<128, true ><<<nb_sp, 256>>>(T2, T1, HR, N_);
        }
        gh_k<<<nb_g, 256, smem_gh>>>(HR, T1, T2, Wh0 + WH, bh0 + 2 * HID, H1, N_);

        // ---- layer 1 (input = H1, F=32) ----
        spmm_k<128, false><<<nb_sp, 256>>>(T1b, H1, nullptr, N_);
        spmm_k<128, true ><<<nb_sp, 256>>>(T2b, T1b, H1, N_);
        gx_k<HID><<<nb_g, 256, smem_gx32>>>(H1, T1b, T2b, Wx1, bx1, N_);
        if (t == 0) {
            zr_k<<<nb_g, 256, smem_zr>>>(H2, T1, T2, Wh1, bh1, N_);  // basis(H2)==0
            // basis(HR)==0 too (HR=H2*R=0): T1/T2 still zero
        } else {
            spmm_k<128, false><<<nb_sp, 256>>>(T1, H2, nullptr, N_);
            spmm_k<128, true ><<<nb_sp, 256>>>(T2, T1, H2, N_);
            zr_k<<<nb_g, 256, smem_zr>>>(H2, T1, T2, Wh1, bh1, N_);
            spmm_k<128, false><<<nb_sp, 256>>>(T1, HR, nullptr, N_);
            spmm_k<128, true ><<<nb_sp, 256>>>(T2, T1, HR, N_);
        }
        gh_k<<<nb_g, 256, smem_gh>>>(HR, T1, T2, Wh1 + WH, bh1 + 2 * HID, H2, N_);
    }

    musig_k<<<(N_ * BB + 255) / 256, 256>>>(H2, muW, mub, sgW, sgb, out, N_);
    sum_k<<<256, 128>>>(H2, N_);
    mix_k<<<1, 128>>>(out, N_);
}

// round 14
// speedup vs baseline: 1.5607x; 1.5607x over previous
#include <cuda_runtime.h>
#include <cuda_fp16.h>

#define BB   4
#define TT   12
#define FIN  8
#define HID  32
#define KORD 3
#define NMAX 50048
#define EMAX 2000128
#define FULLM 0xffffffffu

// ---------------- scratch (device globals; no runtime allocation) ----------------
__device__ float  g_deg[NMAX];
__device__ float  g_dinv[NMAX];
__device__ float  g_diag[NMAX];
__device__ int    g_row[EMAX];
__device__ int    g_col[EMAX];
__device__ int    g_cnt[NMAX];
__device__ int    g_cur[NMAX];
__device__ int    g_off[NMAX + 1];
__device__ float2 g_edge[EMAX];                 // (bitcast src, norm weight)
__device__ int    g_idx64;
__device__ float  g_X  [NMAX * FIN * BB];       // [n][f][b]
__device__ float  g_T1 [NMAX * HID * BB];
__device__ float  g_T2 [NMAX * HID * BB];
__device__ float  g_T1b[NMAX * HID * BB];       // persisted basis(H1) hop 1
__device__ float  g_T2b[NMAX * HID * BB];       // persisted basis(H1) hop 2
__device__ float  g_gx [NMAX * 3 * HID * BB];   // [n][g][o][b]
__device__ float  g_H1 [NMAX * HID * BB];
__device__ float  g_H2 [NMAX * HID * BB];
__device__ float  g_Zb [NMAX * HID * BB];
__device__ float  g_HR [NMAX * HID * BB];
__device__ float  g_S  [HID * BB];
// half mirrors for gather payloads (uint2 = 4 halves per lane)
__device__ uint2  g_H1h[NMAX * 32];
__device__ uint2  g_H2h[NMAX * 32];
__device__ uint2  g_HRh[NMAX * 32];
__device__ uint2  g_T1h[NMAX * 32];

__device__ __forceinline__ float sigm(float x) { return 1.f / (1.f + expf(-x)); }
__device__ __forceinline__ float softplusf(float x) {
    return (x > 20.f) ? x : log1pf(expf(x));
}
__device__ __forceinline__ float2 h2f(unsigned h) {
    __half2 hh = *reinterpret_cast<__half2*>(&h);
    return __half22float2(hh);
}
__device__ __forceinline__ unsigned f2h(float a, float b) {
    __half2 hh = __floats2half2_rn(a, b);
    return *reinterpret_cast<unsigned*>(&hh);
}
__device__ __forceinline__ uint2 pack4(float4 v) {
    return make_uint2(f2h(v.x, v.y), f2h(v.z, v.w));
}

// ---------------- setup kernels ----------------
__global__ void detect_k(const int* __restrict__ ei32, int n_words) {
    int allzero = 1;
    int lim = n_words < 256 ? n_words : 256;
    for (int i = 1; i < lim; i += 2)
        if (ei32[i] != 0) { allzero = 0; break; }
    g_idx64 = allzero;
}

__global__ void edge_init_k(const void* __restrict__ ei,
                            const float* __restrict__ ew, int E) {
    int e = blockIdx.x * blockDim.x + threadIdx.x;
    if (e >= E) return;
    int r, c;
    if (g_idx64) {
        const long long* p = (const long long*)ei;
        r = (int)p[e];
        c = (int)p[E + e];
    } else {
        const int* p = (const int*)ei;
        r = p[e];
        c = p[E + e];
    }
    g_row[e] = r;
    g_col[e] = c;
    atomicAdd(&g_deg[r], ew[e]);
    atomicAdd(&g_cnt[c], 1);
}

__global__ void node_prep_k(int N_) {
    int n = blockIdx.x * blockDim.x + threadIdx.x;
    if (n >= N_) return;
    float d = g_deg[n];
    if (d > 0.f) { g_dinv[n] = rsqrtf(d); g_diag[n] = 0.f; }
    else         { g_dinv[n] = 0.f;       g_diag[n] = -1.f; }
}

__global__ void scan_k(int N_) {
    __shared__ int part[1024];
    int tid = threadIdx.x;
    int chunk = (N_ + 1023) / 1024;
    int start = tid * chunk;
    int end = min(start + chunk, N_);
    if (end < start) end = start;
    int sum = 0;
    for (int i = start; i < end; i++) sum += g_cnt[i];
    part[tid] = sum;
    __syncthreads();
    for (int off = 1; off < 1024; off <<= 1) {
        int v = (tid >= off) ? part[tid - off] : 0;
        __syncthreads();
        part[tid] += v;
        __syncthreads();
    }
    int excl = part[tid] - sum;
    int run = excl;
    for (int i = start; i < end; i++) { g_off[i] = run; run += g_cnt[i]; }
    if (tid == 1023) g_off[N_] = part[1023];
}

__global__ void fill_k(const float* __restrict__ ew, int E) {
    int e = blockIdx.x * blockDim.x + threadIdx.x;
    if (e >= E) return;
    int r = g_row[e], c = g_col[e];
    int pos = g_off[c] + atomicAdd(&g_cur[c], 1);
    g_edge[pos] = make_float2(__int_as_float(r), -ew[e] * g_dinv[r] * g_dinv[c]);
}

__global__ void xgather_k(const float* __restrict__ in, int t, int N_) {
    int tid = blockIdx.x * blockDim.x + threadIdx.x;
    if (tid >= N_ * FIN * BB) return;
    int b = tid / (N_ * FIN);
    int rem = tid - b * (N_ * FIN);
    int n = rem / FIN;
    int f = rem - n * FIN;
    g_X[(n * FIN + f) * BB + b] = in[(((long long)b * TT + t) * N_ + n) * FIN + f];
}

__global__ void zero2_k(float* __restrict__ a, float* __restrict__ b, int nfloat4) {
    int i = blockIdx.x * blockDim.x + threadIdx.x;
    if (i >= nfloat4) return;
    ((float4*)a)[i] = make_float4(0.f, 0.f, 0.f, 0.f);
    ((float4*)b)[i] = make_float4(0.f, 0.f, 0.f, 0.f);
}

// ---------------- fp32 SpMM (layer-0 input, F=8) ----------------
template <bool CHEB>
__global__ void spmm32_k(float* __restrict__ out, const float* __restrict__ x,
                         const float* __restrict__ t0, int N_) {
    int gw = (blockIdx.x * blockDim.x + threadIdx.x) >> 5;
    int lane = threadIdx.x & 31;
    if (gw >= N_) return;
    int o0 = g_off[gw], o1 = g_off[gw + 1];
    float acc = 0.f;
    for (int base = o0; base < o1; base += 32) {
        int idx = base + lane;
        int s = 0; float w = 0.f;
        if (idx < o1) {
            float2 e = g_edge[idx];
            s = __float_as_int(e.x); w = e.y;
        }
        int m = min(32, o1 - base);
        int j = 0;
        for (; j + 3 < m; j += 4) {
            int   s0 = __shfl_sync(FULLM, s, j);
            int   s1 = __shfl_sync(FULLM, s, j + 1);
            int   s2 = __shfl_sync(FULLM, s, j + 2);
            int   s3 = __shfl_sync(FULLM, s, j + 3);
            float w0 = __shfl_sync(FULLM, w, j);
            float w1 = __shfl_sync(FULLM, w, j + 1);
            float w2 = __shfl_sync(FULLM, w, j + 2);
            float w3 = __shfl_sync(FULLM, w, j + 3);
            float v0 = x[s0 * 32 + lane];
            float v1 = x[s1 * 32 + lane];
            float v2 = x[s2 * 32 + lane];
            float v3 = x[s3 * 32 + lane];
            acc = fmaf(w0, v0, acc);
            acc = fmaf(w1, v1, acc);
            acc = fmaf(w2, v2, acc);
            acc = fmaf(w3, v3, acc);
        }
        for (; j < m; j++) {
            int   sj = __shfl_sync(FULLM, s, j);
            float wj = __shfl_sync(FULLM, w, j);
            acc = fmaf(wj, x[sj * 32 + lane], acc);
        }
    }
    acc = fmaf(g_diag[gw], x[gw * 32 + lane], acc);
    if (CHEB) acc = 2.f * acc - t0[gw * 32 + lane];
    out[gw * 32 + lane] = acc;
}

// ---------------- half-payload SpMM, F=128 ----------------
// hop1: gather xh (half), write fp32 out + half out16 (feeds hop2 gather)
// hop2 (CHEB): gather xh, epilogue 2*acc - t0(fp32), write fp32 out only
template <bool CHEB>
__global__ void spmmh_k(float* __restrict__ out, uint2* __restrict__ out16,
                        const uint2* __restrict__ xh, const float* __restrict__ t0,
                        int N_) {
    int gw = (blockIdx.x * blockDim.x + threadIdx.x) >> 5;
    int lane = threadIdx.x & 31;
    if (gw >= N_) return;
    int o0 = g_off[gw], o1 = g_off[gw + 1];
    float4 acc = make_float4(0.f, 0.f, 0.f, 0.f);
    for (int base = o0; base < o1; base += 32) {
        int idx = base + lane;
        int s = 0; float w = 0.f;
        if (idx < o1) {
            float2 e = g_edge[idx];
            s = __float_as_int(e.x); w = e.y;
        }
        int m = min(32, o1 - base);
        int j = 0;
        for (; j + 3 < m; j += 4) {
            int   s0 = __shfl_sync(FULLM, s, j);
            int   s1 = __shfl_sync(FULLM, s, j + 1);
            int   s2 = __shfl_sync(FULLM, s, j + 2);
            int   s3 = __shfl_sync(FULLM, s, j + 3);
            float w0 = __shfl_sync(FULLM, w, j);
            float w1 = __shfl_sync(FULLM, w, j + 1);
            float w2 = __shfl_sync(FULLM, w, j + 2);
            float w3 = __shfl_sync(FULLM, w, j + 3);
            uint2 v0 = xh[s0 * 32 + lane];
            uint2 v1 = xh[s1 * 32 + lane];
            uint2 v2 = xh[s2 * 32 + lane];
            uint2 v3 = xh[s3 * 32 + lane];
            float2 a, b;
            a = h2f(v0.x); b = h2f(v0.y);
            acc.x = fmaf(w0, a.x, acc.x); acc.y = fmaf(w0, a.y, acc.y);
            acc.z = fmaf(w0, b.x, acc.z); acc.w = fmaf(w0, b.y, acc.w);
            a = h2f(v1.x); b = h2f(v1.y);
            acc.x = fmaf(w1, a.x, acc.x); acc.y = fmaf(w1, a.y, acc.y);
            acc.z = fmaf(w1, b.x, acc.z); acc.w = fmaf(w1, b.y, acc.w);
            a = h2f(v2.x); b = h2f(v2.y);
            acc.x = fmaf(w2, a.x, acc.x); acc.y = fmaf(w2, a.y, acc.y);
            acc.z = fmaf(w2, b.x, acc.z); acc.w = fmaf(w2, b.y, acc.w);
            a = h2f(v3.x); b = h2f(v3.y);
            acc.x = fmaf(w3, a.x, acc.x); acc.y = fmaf(w3, a.y, acc.y);
            acc.z = fmaf(w3, b.x, acc.z); acc.w = fmaf(w3, b.y, acc.w);
        }
        for (; j < m; j++) {
            int   sj = __shfl_sync(FULLM, s, j);
            float wj = __shfl_sync(FULLM, w, j);
            uint2 v = xh[sj * 32 + lane];
            float2 a = h2f(v.x), b = h2f(v.y);
            acc.x = fmaf(wj, a.x, acc.x); acc.y = fmaf(wj, a.y, acc.y);
            acc.z = fmaf(wj, b.x, acc.z); acc.w = fmaf(wj, b.y, acc.w);
        }
    }
    {
        float dg = g_diag[gw];
        uint2 dv = xh[gw * 32 + lane];
        float2 a = h2f(dv.x), b = h2f(dv.y);
        acc.x = fmaf(dg, a.x, acc.x); acc.y = fmaf(dg, a.y, acc.y);
        acc.z = fmaf(dg, b.x, acc.z); acc.w = fmaf(dg, b.y, acc.w);
    }
    if (CHEB) {
        float4 p = ((const float4*)t0)[gw * 32 + lane];
        acc.x = 2.f * acc.x - p.x; acc.y = 2.f * acc.y - p.y;
        acc.z = 2.f * acc.z - p.z; acc.w = 2.f * acc.w - p.w;
    }
    ((float4*)out)[gw * 32 + lane] = acc;
    if (!CHEB) out16[gw * 32 + lane] = pack4(acc);
}

// ---------------- gate kernels (grid-stride; weights loaded once per block) ----------------
template <int F>
__global__ void gx_k(const float* __restrict__ T0, const float* __restrict__ T1v,
                     const float* __restrict__ T2v, const float* __restrict__ Wx,
                     const float* __restrict__ bx, int N_) {
    constexpr int KF = KORD * F;
    extern __shared__ float sm[];
    float* wsh = sm;
    float* insh = sm + 3 * KF * 32;
    int tid = threadIdx.x;
    for (int i = tid; i < 3 * KF * 32; i += blockDim.x) wsh[i] = Wx[i];
    __syncthreads();
    int wid = tid >> 5, lane = tid & 31;
    float4* in4 = ((float4*)insh) + wid * KF;
    const float* Ts[3] = {T0, T1v, T2v};
    for (int n0 = blockIdx.x * 8; n0 < N_; n0 += gridDim.x * 8) {
        int n = n0 + wid;
        if (n >= N_) break;
        for (int k = 0; k < 3; k++)
            for (int i = lane; i < F; i += 32)
                in4[k * F + i] = ((const float4*)Ts[k])[n * F + i];
        __syncwarp();
        for (int g = 0; g < 3; g++) {
            float ax = 0.f, ay = 0.f, az = 0.f, aw = 0.f;
            const float* wg = wsh + g * KF * 32 + lane;
#pragma unroll 4
            for (int i = 0; i < KF; i++) {
                float w = wg[i * 32];
                float4 v = in4[i];
                ax = fmaf(w, v.x, ax); ay = fmaf(w, v.y, ay);
                az = fmaf(w, v.z, az); aw = fmaf(w, v.w, aw);
            }
            float bb = bx[g * 32 + lane];
            ((float4*)g_gx)[(n * 3 + g) * 32 + lane] =
                make_float4(ax + bb, ay + bb, az + bb, aw + bb);
        }
        __syncwarp();
    }
}

__global__ void zr_k(const float* __restrict__ T0, const float* __restrict__ T1v,
                     const float* __restrict__ T2v, const float* __restrict__ Wh,
                     const float* __restrict__ bh, uint2* __restrict__ HRh, int N_) {
    constexpr int F = HID, KF = KORD * HID;
    extern __shared__ float sm[];
    float* wsh = sm;
    float* insh = sm + 2 * KF * 32;
    int tid = threadIdx.x;
    for (int i = tid; i < 2 * KF * 32; i += blockDim.x) wsh[i] = Wh[i];
    __syncthreads();
    int wid = tid >> 5, lane = tid & 31;
    float4* in4 = ((float4*)insh) + wid * KF;
    const float* Ts[3] = {T0, T1v, T2v};
    for (int n0 = blockIdx.x * 8; n0 < N_; n0 += gridDim.x * 8) {
        int n = n0 + wid;
        if (n >= N_) break;
        for (int k = 0; k < 3; k++)
            for (int i = lane; i < F; i += 32)
                in4[k * F + i] = ((const float4*)Ts[k])[n * F + i];
        __syncwarp();
        float4 az = make_float4(0.f, 0.f, 0.f, 0.f);
        float4 ar = make_float4(0.f, 0.f, 0.f, 0.f);
        const float* wz = wsh + lane;
        const float* wr = wsh + KF * 32 + lane;
#pragma unroll 4
        for (int i = 0; i < KF; i++) {
            float4 v = in4[i];
            float a = wz[i * 32];
            az.x = fmaf(a, v.x, az.x); az.y = fmaf(a, v.y, az.y);
            az.z = fmaf(a, v.z, az.z); az.w = fmaf(a, v.w, az.w);
            float b = wr[i * 32];
            ar.x = fmaf(b, v.x, ar.x); ar.y = fmaf(b, v.y, ar.y);
            ar.z = fmaf(b, v.z, ar.z); ar.w = fmaf(b, v.w, ar.w);
        }
        float4 gx0 = ((const float4*)g_gx)[(n * 3 + 0) * 32 + lane];
        float4 gx1 = ((const float4*)g_gx)[(n * 3 + 1) * 32 + lane];
        float bz = bh[lane], br = bh[32 + lane];
        float4 H = in4[lane];
        float4 Z, HR;
        Z.x = sigm(gx0.x + az.x + bz); Z.y = sigm(gx0.y + az.y + bz);
        Z.z = sigm(gx0.z + az.z + bz); Z.w = sigm(gx0.w + az.w + bz);
        HR.x = H.x * sigm(gx1.x + ar.x + br);
        HR.y = H.y * sigm(gx1.y + ar.y + br);
        HR.z = H.z * sigm(gx1.z + ar.z + br);
        HR.w = H.w * sigm(gx1.w + ar.w + br);
        ((float4*)g_Zb)[n * 32 + lane] = Z;
        ((float4*)g_HR)[n * 32 + lane] = HR;
        HRh[n * 32 + lane] = pack4(HR);
        __syncwarp();
    }
}

__global__ void gh_k(const float* __restrict__ T0, const float* __restrict__ T1v,
                     const float* __restrict__ T2v, const float* __restrict__ Wh2,
                     const float* __restrict__ bh2, float* __restrict__ Hio,
                     uint2* __restrict__ Hh, int N_) {
    constexpr int F = HID, KF = KORD * HID;
    extern __shared__ float sm[];
    float* wsh = sm;
    float* insh = sm + KF * 32;
    int tid = threadIdx.x;
    for (int i = tid; i < KF * 32; i += blockDim.x) wsh[i] = Wh2[i];
    __syncthreads();
    int wid = tid >> 5, lane = tid & 31;
    float4* in4 = ((float4*)insh) + wid * KF;
    const float* Ts[3] = {T0, T1v, T2v};
    for (int n0 = blockIdx.x * 8; n0 < N_; n0 += gridDim.x * 8) {
        int n = n0 + wid;
        if (n >= N_) break;
        for (int k = 0; k < 3; k++)
            for (int i = lane; i < F; i += 32)
                in4[k * F + i] = ((const float4*)Ts[k])[n * F + i];
        __syncwarp();
        float4 ah = make_float4(0.f, 0.f, 0.f, 0.f);
        const float* wg = wsh + lane;
#pragma unroll 4
        for (int i = 0; i < KF; i++) {
            float4 v = in4[i];
            float a = wg[i * 32];
            ah.x = fmaf(a, v.x, ah.x); ah.y = fmaf(a, v.y, ah.y);
            ah.z = fmaf(a, v.z, ah.z); ah.w = fmaf(a, v.w, ah.w);
        }
        float4 gx2 = ((const float4*)g_gx)[(n * 3 + 2) * 32 + lane];
        float b2 = bh2[lane];
        float4 Z = ((const float4*)g_Zb)[n * 32 + lane];
        float4 H = ((const float4*)Hio)[n * 32 + lane];
        float4 Hn;
        Hn.x = Z.x * H.x + (1.f - Z.x) * tanhf(gx2.x + ah.x + b2);
        Hn.y = Z.y * H.y + (1.f - Z.y) * tanhf(gx2.y + ah.y + b2);
        Hn.z = Z.z * H.z + (1.f - Z.z) * tanhf(gx2.z + ah.z + b2);
        Hn.w = Z.w * H.w + (1.f - Z.w) * tanhf(gx2.w + ah.w + b2);
        ((float4*)Hio)[n * 32 + lane] = Hn;
        Hh[n * 32 + lane] = pack4(Hn);
        __syncwarp();
    }
}

// ---------------- heads ----------------
__global__ void musig_k(const float* __restrict__ H2, const float* __restrict__ muW,
                        const float* __restrict__ mub, const float* __restrict__ sgW,
                        const float* __restrict__ sgb, float* __restrict__ out, int N_) {
    int tid = blockIdx.x * blockDim.x + threadIdx.x;
    if (tid >= N_ * BB) return;
    int b = tid & 3;
    int n = tid >> 2;
    float a0 = 0.f, a1 = 0.f, s0 = 0.f, s1 = 0.f;
#pragma unroll
    for (int i = 0; i < HID; i++) {
        float h = H2[(n * HID + i) * BB + b];
        a0 = fmaf(h, muW[i * 2 + 0], a0);
        a1 = fmaf(h, muW[i * 2 + 1], a1);
        s0 = fmaf(h, sgW[i * 2 + 0], s0);
        s1 = fmaf(h, sgW[i * 2 + 1], s1);
    }
    a0 += mub[0]; a1 += mub[1]; s0 += sgb[0]; s1 += sgb[1];
    out[((long long)b * N_ + n) * 2 + 0] = sigm(a0);
    out[((long long)b * N_ + n) * 2 + 1] = sigm(a1);
    float* so = out + (long long)BB * N_ * 2;
    so[((long long)b * N_ + n) * 2 + 0] = softplusf(s0);
    so[((long long)b * N_ + n) * 2 + 1] = softplusf(s1);
}

__global__ void sum_k(const float* __restrict__ H2, int N_) {
    int tid = threadIdx.x;
    int per = (N_ + gridDim.x - 1) / gridDim.x;
    int n0 = blockIdx.x * per;
    int n1 = min(n0 + per, N_);
    float acc = 0.f;
    for (int n = n0; n < n1; n++) acc += H2[n * 128 + tid];
    atomicAdd(&g_S[tid], acc);
}

__global__ void mix_k(float* __restrict__ out, int N_) {
    int lane = threadIdx.x & 31;
    int b = threadIdx.x >> 5;
    float v = g_S[lane * BB + b] / (float)N_;
    float m = v;
    for (int o = 16; o; o >>= 1) m = fmaxf(m, __shfl_xor_sync(FULLM, m, o));
    float e = expf(v - m);
    float s = e;
    for (int o = 16; o; o >>= 1) s += __shfl_xor_sync(FULLM, s, o);
    out[(long long)BB * N_ * 4 + b * HID + lane] = e / s;
}

// ---------------- launcher ----------------
extern "C" void kernel_launch(void* const* d_in, const int* in_sizes, int n_in,
                              void* d_out, int out_size) {
    const float* in_tensor = (const float*)d_in[0];
    const void*  ei  = d_in[1];
    const float* ew  = (const float*)d_in[2];
    const float* Wx0 = (const float*)d_in[3];
    const float* Wh0 = (const float*)d_in[4];
    const float* bx0 = (const float*)d_in[5];
    const float* bh0 = (const float*)d_in[6];
    const float* Wx1 = (const float*)d_in[7];
    const float* Wh1 = (const float*)d_in[8];
    const float* bx1 = (const float*)d_in[9];
    const float* bh1 = (const float*)d_in[10];
    const float* muW = (const float*)d_in[11];
    const float* mub = (const float*)d_in[12];
    const float* sgW = (const float*)d_in[13];
    const float* sgb = (const float*)d_in[14];
    float* out = (float*)d_out;

    int E  = in_sizes[1] / 2;
    int N_ = in_sizes[0] / (BB * TT * FIN);

    void *pdeg, *pcnt, *pcur, *pS, *pH1, *pH2, *pT1, *pT2, *pT1b, *pT2b, *pX, *pHR;
    void *pH1h, *pH2h, *pHRh, *pT1h;
    cudaGetSymbolAddress(&pdeg, g_deg);
    cudaGetSymbolAddress(&pcnt, g_cnt);
    cudaGetSymbolAddress(&pcur, g_cur);
    cudaGetSymbolAddress(&pS,   g_S);
    cudaGetSymbolAddress(&pH1,  g_H1);
    cudaGetSymbolAddress(&pH2,  g_H2);
    cudaGetSymbolAddress(&pT1,  g_T1);
    cudaGetSymbolAddress(&pT2,  g_T2);
    cudaGetSymbolAddress(&pT1b, g_T1b);
    cudaGetSymbolAddress(&pT2b, g_T2b);
    cudaGetSymbolAddress(&pX,   g_X);
    cudaGetSymbolAddress(&pHR,  g_HR);
    cudaGetSymbolAddress(&pH1h, g_H1h);
    cudaGetSymbolAddress(&pH2h, g_H2h);
    cudaGetSymbolAddress(&pHRh, g_HRh);
    cudaGetSymbolAddress(&pT1h, g_T1h);
    float *T1 = (float*)pT1, *T2 = (float*)pT2, *X = (float*)pX;
    float *T1b = (float*)pT1b, *T2b = (float*)pT2b;
    float *H1 = (float*)pH1, *H2 = (float*)pH2, *HR = (float*)pHR;
    uint2 *H1h = (uint2*)pH1h, *H2h = (uint2*)pH2h, *HRh = (uint2*)pHRh, *T1h = (uint2*)pT1h;

    const int smem_gx8  = (3 * KORD * FIN * 32 + 8 * KORD * FIN * 4) * 4;
    const int smem_gx32 = (3 * KORD * HID * 32 + 8 * KORD * HID * 4) * 4;
    const int smem_zr   = (2 * KORD * HID * 32 + 8 * KORD * HID * 4) * 4;
    const int smem_gh   = (1 * KORD * HID * 32 + 8 * KORD * HID * 4) * 4;
    cudaFuncSetAttribute((const void*)gx_k<FIN>, cudaFuncAttributeMaxDynamicSharedMemorySize, 65536);
    cudaFuncSetAttribute((const void*)gx_k<HID>, cudaFuncAttributeMaxDynamicSharedMemorySize, 65536);
    cudaFuncSetAttribute((const void*)zr_k,      cudaFuncAttributeMaxDynamicSharedMemorySize, 65536);
    cudaFuncSetAttribute((const void*)gh_k,      cudaFuncAttributeMaxDynamicSharedMemorySize, 65536);

    cudaMemsetAsync(pdeg, 0, (size_t)N_ * 4);
    cudaMemsetAsync(pcnt, 0, (size_t)N_ * 4);
    cudaMemsetAsync(pcur, 0, (size_t)N_ * 4);
    cudaMemsetAsync(pS,   0, 128 * 4);
    cudaMemsetAsync(pH1,  0, (size_t)N_ * 128 * 4);
    cudaMemsetAsync(pH2,  0, (size_t)N_ * 128 * 4);
    cudaMemsetAsync(pT1b, 0, (size_t)N_ * 128 * 4);
    cudaMemsetAsync(pT2b, 0, (size_t)N_ * 128 * 4);

    int ebl = (E + 255) / 256;
    int nb_sp = (N_ * 32 + 255) / 256;   // one warp per node
    int nb_g  = 592;
    int nzf   = (N_ * 32 + 255) / 256;
    const int WH = 2 * KORD * HID * HID;

    detect_k<<<1, 1>>>((const int*)ei, in_sizes[1]);
    edge_init_k<<<ebl, 256>>>(ei, ew, E);
    node_prep_k<<<(N_ + 255) / 256, 256>>>(N_);
    scan_k<<<1, 1024>>>(N_);
    fill_k<<<ebl, 256>>>(ew, E);

    for (int t = 0; t < TT; t++) {
        // ---- layer 0 (input F=8, fp32 path) ----
        xgather_k<<<(N_ * FIN * BB + 255) / 256, 256>>>(in_tensor, t, N_);
        spmm32_k<false><<<nb_sp, 256>>>(T1, X, nullptr, N_);
        spmm32_k<true ><<<nb_sp, 256>>>(T2, T1, X, N_);
        gx_k<FIN><<<nb_g, 256, smem_gx8>>>(X, T1, T2, Wx0, bx0, N_);
        // basis(H1) reused from layer 1 of prev step (zeroed at setup for t=0)
        zr_k<<<nb_g, 256, smem_zr>>>(H1, T1b, T2b, Wh0, bh0, HRh, N_);
        if (t == 0) {
            zero2_k<<<nzf, 256>>>(T1, T2, N_ * 32);     // basis(HR)==0 at t=0
        } else {
            spmmh_k<false><<<nb_sp, 256>>>(T1, T1h, HRh, nullptr, N_);
            spmmh_k<true ><<<nb_sp, 256>>>(T2, nullptr, T1h, HR, N_);
        }
        gh_k<<<nb_g, 256, smem_gh>>>(HR, T1, T2, Wh0 + WH, bh0 + 2 * HID, H1, H1h, N_);

        // ---- layer 1 (input = H1, F=32) ----
        spmmh_k<false><<<nb_sp, 256>>>(T1b, T1h, H1h, nullptr, N_);
        spmmh_k<true ><<<nb_sp, 256>>>(T2b, nullptr, T1h, H1, N_);
        gx_k<HID><<<nb_g, 256, smem_gx32>>>(H1, T1b, T2b, Wx1, bx1, N_);
        if (t == 0) {
            zr_k<<<nb_g, 256, smem_zr>>>(H2, T1, T2, Wh1, bh1, HRh, N_);  // basis(H2)==0
            // basis(HR)==0 too (HR=H2*R=0): T1/T2 still zero
        } else {
            spmmh_k<false><<<nb_sp, 256>>>(T1, T1h, H2h, nullptr, N_);
            spmmh_k<true ><<<nb_sp, 256>>>(T2, nullptr, T1h, H2, N_);
            zr_k<<<nb_g, 256, smem_zr>>>(H2, T1, T2, Wh1, bh1, HRh, N_);
            spmmh_k<false><<<nb_sp, 256>>>(T1, T1h, HRh, nullptr, N_);
            spmmh_k<true ><<<nb_sp, 256>>>(T2, nullptr, T1h, HR, N_);
        }
        gh_k<<<nb_g, 256, smem_gh>>>(HR, T1, T2, Wh1 + WH, bh1 + 2 * HID, H2, H2h, N_);
    }

    musig_k<<<(N_ * BB + 255) / 256, 256>>>(H2, muW, mub, sgW, sgb, out, N_);
    sum_k<<<256, 128>>>(H2, N_);
    mix_k<<<1, 128>>>(out, N_);
}

// round 15
// speedup vs baseline: 1.6075x; 1.0299x over previous
#include <cuda_runtime.h>
#include <cuda_fp16.h>

#define BB   4
#define TT   12
#define FIN  8
#define HID  32
#define KORD 3
#define NMAX 50048
#define EMAX 2000128
#define FULLM 0xffffffffu

// ---------------- scratch (device globals; no runtime allocation) ----------------
__device__ float  g_deg[NMAX];
__device__ float  g_dinv[NMAX];
__device__ float  g_diag[NMAX];
__device__ int    g_row[EMAX];
__device__ int    g_col[EMAX];
__device__ int    g_cnt[NMAX];
__device__ int    g_cur[NMAX];
__device__ int    g_off[NMAX + 1];
__device__ float2 g_edge[EMAX];                 // (bitcast src, norm weight)
__device__ int    g_idx64;
__device__ float  g_X  [NMAX * FIN * BB];       // [n][f][b]
__device__ float  g_T1 [NMAX * HID * BB];
__device__ float  g_T2 [NMAX * HID * BB];
__device__ float  g_T1b[NMAX * HID * BB];       // persisted basis(H1) hop 1
__device__ float  g_T2b[NMAX * HID * BB];       // persisted basis(H1) hop 2
__device__ float  g_gx [NMAX * 3 * HID * BB];   // [n][g][o][b]
__device__ float  g_H1 [NMAX * HID * BB];
__device__ float  g_H2 [NMAX * HID * BB];
__device__ float  g_Zb [NMAX * HID * BB];
__device__ float  g_HR [NMAX * HID * BB];
__device__ float  g_S  [HID * BB];
// half mirrors for gather payloads (uint2 = 4 halves per lane)
__device__ uint2  g_H1h[NMAX * 32];
__device__ uint2  g_H2h[NMAX * 32];
__device__ uint2  g_HRh[NMAX * 32];
__device__ uint2  g_T1h[NMAX * 32];

__device__ __forceinline__ float sigm(float x) { return 1.f / (1.f + expf(-x)); }
__device__ __forceinline__ float softplusf(float x) {
    return (x > 20.f) ? x : log1pf(expf(x));
}
__device__ __forceinline__ float2 h2f(unsigned h) {
    __half2 hh = *reinterpret_cast<__half2*>(&h);
    return __half22float2(hh);
}
__device__ __forceinline__ unsigned f2h(float a, float b) {
    __half2 hh = __floats2half2_rn(a, b);
    return *reinterpret_cast<unsigned*>(&hh);
}
__device__ __forceinline__ uint2 pack4(float4 v) {
    return make_uint2(f2h(v.x, v.y), f2h(v.z, v.w));
}

// warp gather (half payload): returns weighted sum over node gw's in-edges
__device__ __forceinline__ float4 gather_h(const uint2* __restrict__ xh,
                                           int gw, int lane) {
    int o0 = g_off[gw], o1 = g_off[gw + 1];
    float4 acc = make_float4(0.f, 0.f, 0.f, 0.f);
    for (int base = o0; base < o1; base += 32) {
        int idx = base + lane;
        int s = 0; float w = 0.f;
        if (idx < o1) {
            float2 e = g_edge[idx];
            s = __float_as_int(e.x); w = e.y;
        }
        int m = min(32, o1 - base);
        int j = 0;
        for (; j + 3 < m; j += 4) {
            int   s0 = __shfl_sync(FULLM, s, j);
            int   s1 = __shfl_sync(FULLM, s, j + 1);
            int   s2 = __shfl_sync(FULLM, s, j + 2);
            int   s3 = __shfl_sync(FULLM, s, j + 3);
            float w0 = __shfl_sync(FULLM, w, j);
            float w1 = __shfl_sync(FULLM, w, j + 1);
            float w2 = __shfl_sync(FULLM, w, j + 2);
            float w3 = __shfl_sync(FULLM, w, j + 3);
            uint2 v0 = xh[s0 * 32 + lane];
            uint2 v1 = xh[s1 * 32 + lane];
            uint2 v2 = xh[s2 * 32 + lane];
            uint2 v3 = xh[s3 * 32 + lane];
            float2 a, b;
            a = h2f(v0.x); b = h2f(v0.y);
            acc.x = fmaf(w0, a.x, acc.x); acc.y = fmaf(w0, a.y, acc.y);
            acc.z = fmaf(w0, b.x, acc.z); acc.w = fmaf(w0, b.y, acc.w);
            a = h2f(v1.x); b = h2f(v1.y);
            acc.x = fmaf(w1, a.x, acc.x); acc.y = fmaf(w1, a.y, acc.y);
            acc.z = fmaf(w1, b.x, acc.z); acc.w = fmaf(w1, b.y, acc.w);
            a = h2f(v2.x); b = h2f(v2.y);
            acc.x = fmaf(w2, a.x, acc.x); acc.y = fmaf(w2, a.y, acc.y);
            acc.z = fmaf(w2, b.x, acc.z); acc.w = fmaf(w2, b.y, acc.w);
            a = h2f(v3.x); b = h2f(v3.y);
            acc.x = fmaf(w3, a.x, acc.x); acc.y = fmaf(w3, a.y, acc.y);
            acc.z = fmaf(w3, b.x, acc.z); acc.w = fmaf(w3, b.y, acc.w);
        }
        for (; j < m; j++) {
            int   sj = __shfl_sync(FULLM, s, j);
            float wj = __shfl_sync(FULLM, w, j);
            uint2 v = xh[sj * 32 + lane];
            float2 a = h2f(v.x), b = h2f(v.y);
            acc.x = fmaf(wj, a.x, acc.x); acc.y = fmaf(wj, a.y, acc.y);
            acc.z = fmaf(wj, b.x, acc.z); acc.w = fmaf(wj, b.y, acc.w);
        }
    }
    return acc;
}

// ---------------- setup kernels ----------------
__global__ void detect_k(const int* __restrict__ ei32, int n_words) {
    int allzero = 1;
    int lim = n_words < 256 ? n_words : 256;
    for (int i = 1; i < lim; i += 2)
        if (ei32[i] != 0) { allzero = 0; break; }
    g_idx64 = allzero;
}

__global__ void edge_init_k(const void* __restrict__ ei,
                            const float* __restrict__ ew, int E) {
    int e = blockIdx.x * blockDim.x + threadIdx.x;
    if (e >= E) return;
    int r, c;
    if (g_idx64) {
        const long long* p = (const long long*)ei;
        r = (int)p[e];
        c = (int)p[E + e];
    } else {
        const int* p = (const int*)ei;
        r = p[e];
        c = p[E + e];
    }
    g_row[e] = r;
    g_col[e] = c;
    atomicAdd(&g_deg[r], ew[e]);
    atomicAdd(&g_cnt[c], 1);
}

__global__ void node_prep_k(int N_) {
    int n = blockIdx.x * blockDim.x + threadIdx.x;
    if (n >= N_) return;
    float d = g_deg[n];
    if (d > 0.f) { g_dinv[n] = rsqrtf(d); g_diag[n] = 0.f; }
    else         { g_dinv[n] = 0.f;       g_diag[n] = -1.f; }
}

__global__ void scan_k(int N_) {
    __shared__ int part[1024];
    int tid = threadIdx.x;
    int chunk = (N_ + 1023) / 1024;
    int start = tid * chunk;
    int end = min(start + chunk, N_);
    if (end < start) end = start;
    int s0 = 0, s1 = 0, s2 = 0, s3 = 0;
    int i = start;
    for (; i + 3 < end; i += 4) {
        s0 += g_cnt[i]; s1 += g_cnt[i + 1];
        s2 += g_cnt[i + 2]; s3 += g_cnt[i + 3];
    }
    for (; i < end; i++) s0 += g_cnt[i];
    int sum = s0 + s1 + s2 + s3;
    part[tid] = sum;
    __syncthreads();
    for (int off = 1; off < 1024; off <<= 1) {
        int v = (tid >= off) ? part[tid - off] : 0;
        __syncthreads();
        part[tid] += v;
        __syncthreads();
    }
    int run = part[tid] - sum;
    i = start;
    for (; i + 3 < end; i += 4) {
        int c0 = g_cnt[i], c1 = g_cnt[i + 1], c2 = g_cnt[i + 2], c3 = g_cnt[i + 3];
        g_off[i] = run; run += c0;
        g_off[i + 1] = run; run += c1;
        g_off[i + 2] = run; run += c2;
        g_off[i + 3] = run; run += c3;
    }
    for (; i < end; i++) { g_off[i] = run; run += g_cnt[i]; }
    if (tid == 1023) g_off[N_] = part[1023];
}

__global__ void fill_k(const float* __restrict__ ew, int E) {
    int e = blockIdx.x * blockDim.x + threadIdx.x;
    if (e >= E) return;
    int r = g_row[e], c = g_col[e];
    int pos = g_off[c] + atomicAdd(&g_cur[c], 1);
    g_edge[pos] = make_float2(__int_as_float(r), -ew[e] * g_dinv[r] * g_dinv[c]);
}

__global__ void xgather_k(const float* __restrict__ in, int t, int N_) {
    int tid = blockIdx.x * blockDim.x + threadIdx.x;
    if (tid >= N_ * FIN * BB) return;
    int b = tid / (N_ * FIN);
    int rem = tid - b * (N_ * FIN);
    int n = rem / FIN;
    int f = rem - n * FIN;
    g_X[(n * FIN + f) * BB + b] = in[(((long long)b * TT + t) * N_ + n) * FIN + f];
}

__global__ void zero2_k(float* __restrict__ a, float* __restrict__ b, int nfloat4) {
    int i = blockIdx.x * blockDim.x + threadIdx.x;
    if (i >= nfloat4) return;
    ((float4*)a)[i] = make_float4(0.f, 0.f, 0.f, 0.f);
    ((float4*)b)[i] = make_float4(0.f, 0.f, 0.f, 0.f);
}

// ---------------- fp32 SpMM hop1 (layer-0 input, F=8) ----------------
__global__ void spmm32_k(float* __restrict__ out, const float* __restrict__ x, int N_) {
    int gw = (blockIdx.x * blockDim.x + threadIdx.x) >> 5;
    int lane = threadIdx.x & 31;
    if (gw >= N_) return;
    int o0 = g_off[gw], o1 = g_off[gw + 1];
    float acc = 0.f;
    for (int base = o0; base < o1; base += 32) {
        int idx = base + lane;
        int s = 0; float w = 0.f;
        if (idx < o1) {
            float2 e = g_edge[idx];
            s = __float_as_int(e.x); w = e.y;
        }
        int m = min(32, o1 - base);
        int j = 0;
        for (; j + 3 < m; j += 4) {
            int   s0 = __shfl_sync(FULLM, s, j);
            int   s1 = __shfl_sync(FULLM, s, j + 1);
            int   s2 = __shfl_sync(FULLM, s, j + 2);
            int   s3 = __shfl_sync(FULLM, s, j + 3);
            float w0 = __shfl_sync(FULLM, w, j);
            float w1 = __shfl_sync(FULLM, w, j + 1);
            float w2 = __shfl_sync(FULLM, w, j + 2);
            float w3 = __shfl_sync(FULLM, w, j + 3);
            acc = fmaf(w0, x[s0 * 32 + lane], acc);
            acc = fmaf(w1, x[s1 * 32 + lane], acc);
            acc = fmaf(w2, x[s2 * 32 + lane], acc);
            acc = fmaf(w3, x[s3 * 32 + lane], acc);
        }
        for (; j < m; j++) {
            int   sj = __shfl_sync(FULLM, s, j);
            float wj = __shfl_sync(FULLM, w, j);
            acc = fmaf(wj, x[sj * 32 + lane], acc);
        }
    }
    acc = fmaf(g_diag[gw], x[gw * 32 + lane], acc);
    out[gw * 32 + lane] = acc;
}

// ---------------- half-payload SpMM hop1, F=128 (writes fp32 + half mirror) ----------------
__global__ void spmmh_k(float* __restrict__ out, uint2* __restrict__ out16,
                        const uint2* __restrict__ xh, int N_) {
    int gw = (blockIdx.x * blockDim.x + threadIdx.x) >> 5;
    int lane = threadIdx.x & 31;
    if (gw >= N_) return;
    float4 acc = gather_h(xh, gw, lane);
    float dg = g_diag[gw];
    uint2 dv = xh[gw * 32 + lane];
    float2 a = h2f(dv.x), b = h2f(dv.y);
    acc.x = fmaf(dg, a.x, acc.x); acc.y = fmaf(dg, a.y, acc.y);
    acc.z = fmaf(dg, b.x, acc.z); acc.w = fmaf(dg, b.y, acc.w);
    ((float4*)out)[gw * 32 + lane] = acc;
    out16[gw * 32 + lane] = pack4(acc);
}

// ================= FUSED hop2 + gate kernels (grid-stride, F=128) =================
// Each warp: gather T2[n] from T1h; diag from fp32 T1; cheb epilogue with T0; then
// stage {T0,T1,T2} to smem and run the gate math in-place.

// fused gx (layer1): also writes T2b (persisted basis for next-step zr0)
__global__ void f_gx32_k(const float* __restrict__ T0, const float* __restrict__ T1f,
                         const uint2* __restrict__ xh, float* __restrict__ T2out,
                         const float* __restrict__ Wx, const float* __restrict__ bx,
                         int N_) {
    constexpr int KF = KORD * HID;  // 96
    extern __shared__ float sm[];
    float* wsh = sm;                        // 3*KF*32
    float* insh = sm + 3 * KF * 32;         // 8 warps * KF float4
    int tid = threadIdx.x;
    for (int i = tid; i < 3 * KF * 32; i += blockDim.x) wsh[i] = Wx[i];
    __syncthreads();
    int wid = tid >> 5, lane = tid & 31;
    float4* st4 = ((float4*)insh) + wid * KF;
    float b0 = bx[lane], b1 = bx[32 + lane], b2 = bx[64 + lane];
    for (int n0 = blockIdx.x * 8; n0 < N_; n0 += gridDim.x * 8) {
        int n = n0 + wid;
        if (n >= N_) break;
        float4 acc = gather_h(xh, n, lane);
        float4 t1v = ((const float4*)T1f)[n * 32 + lane];
        float dg = g_diag[n];
        acc.x = fmaf(dg, t1v.x, acc.x); acc.y = fmaf(dg, t1v.y, acc.y);
        acc.z = fmaf(dg, t1v.z, acc.z); acc.w = fmaf(dg, t1v.w, acc.w);
        float4 p = ((const float4*)T0)[n * 32 + lane];
        acc.x = 2.f * acc.x - p.x; acc.y = 2.f * acc.y - p.y;
        acc.z = 2.f * acc.z - p.z; acc.w = 2.f * acc.w - p.w;
        ((float4*)T2out)[n * 32 + lane] = acc;
        st4[lane] = p; st4[32 + lane] = t1v; st4[64 + lane] = acc;
        __syncwarp();
        for (int g = 0; g < 3; g++) {
            float ax = 0.f, ay = 0.f, az = 0.f, aw = 0.f;
            const float* wg = wsh + g * KF * 32 + lane;
#pragma unroll 4
            for (int i = 0; i < KF; i++) {
                float w = wg[i * 32];
                float4 v = st4[i];
                ax = fmaf(w, v.x, ax); ay = fmaf(w, v.y, ay);
                az = fmaf(w, v.z, az); aw = fmaf(w, v.w, aw);
            }
            float bb = (g == 0) ? b0 : (g == 1) ? b1 : b2;
            ((float4*)g_gx)[(n * 3 + g) * 32 + lane] =
                make_float4(ax + bb, ay + bb, az + bb, aw + bb);
        }
        __syncwarp();
    }
}

// fused zr (layer1): T0 = H2; writes Zb, HR, HRh
__global__ void f_zr_k(const float* __restrict__ T0, const float* __restrict__ T1f,
                       const uint2* __restrict__ xh, const float* __restrict__ Wh,
                       const float* __restrict__ bh, uint2* __restrict__ HRh, int N_) {
    constexpr int KF = KORD * HID;
    extern __shared__ float sm[];
    float* wsh = sm;                        // 2*KF*32
    float* insh = sm + 2 * KF * 32;
    int tid = threadIdx.x;
    for (int i = tid; i < 2 * KF * 32; i += blockDim.x) wsh[i] = Wh[i];
    __syncthreads();
    int wid = tid >> 5, lane = tid & 31;
    float4* st4 = ((float4*)insh) + wid * KF;
    float bz = bh[lane], br = bh[32 + lane];
    for (int n0 = blockIdx.x * 8; n0 < N_; n0 += gridDim.x * 8) {
        int n = n0 + wid;
        if (n >= N_) break;
        float4 acc = gather_h(xh, n, lane);
        float4 t1v = ((const float4*)T1f)[n * 32 + lane];
        float dg = g_diag[n];
        acc.x = fmaf(dg, t1v.x, acc.x); acc.y = fmaf(dg, t1v.y, acc.y);
        acc.z = fmaf(dg, t1v.z, acc.z); acc.w = fmaf(dg, t1v.w, acc.w);
        float4 p = ((const float4*)T0)[n * 32 + lane];   // p == H row
        acc.x = 2.f * acc.x - p.x; acc.y = 2.f * acc.y - p.y;
        acc.z = 2.f * acc.z - p.z; acc.w = 2.f * acc.w - p.w;
        st4[lane] = p; st4[32 + lane] = t1v; st4[64 + lane] = acc;
        __syncwarp();
        float4 az = make_float4(0.f, 0.f, 0.f, 0.f);
        float4 ar = make_float4(0.f, 0.f, 0.f, 0.f);
        const float* wz = wsh + lane;
        const float* wr = wsh + KF * 32 + lane;
#pragma unroll 4
        for (int i = 0; i < KF; i++) {
            float4 v = st4[i];
            float a = wz[i * 32];
            az.x = fmaf(a, v.x, az.x); az.y = fmaf(a, v.y, az.y);
            az.z = fmaf(a, v.z, az.z); az.w = fmaf(a, v.w, az.w);
            float b = wr[i * 32];
            ar.x = fmaf(b, v.x, ar.x); ar.y = fmaf(b, v.y, ar.y);
            ar.z = fmaf(b, v.z, ar.z); ar.w = fmaf(b, v.w, ar.w);
        }
        float4 gx0 = ((const float4*)g_gx)[(n * 3 + 0) * 32 + lane];
        float4 gx1 = ((const float4*)g_gx)[(n * 3 + 1) * 32 + lane];
        float4 Z, HR;
        Z.x = sigm(gx0.x + az.x + bz); Z.y = sigm(gx0.y + az.y + bz);
        Z.z = sigm(gx0.z + az.z + bz); Z.w = sigm(gx0.w + az.w + bz);
        HR.x = p.x * sigm(gx1.x + ar.x + br);
        HR.y = p.y * sigm(gx1.y + ar.y + br);
        HR.z = p.z * sigm(gx1.z + ar.z + br);
        HR.w = p.w * sigm(gx1.w + ar.w + br);
        ((float4*)g_Zb)[n * 32 + lane] = Z;
        ((float4*)g_HR)[n * 32 + lane] = HR;
        HRh[n * 32 + lane] = pack4(HR);
        __syncwarp();
    }
}

// fused gh: T0 = HR; updates Hio + half mirror
__global__ void f_gh_k(const float* __restrict__ T0, const float* __restrict__ T1f,
                       const uint2* __restrict__ xh, const float* __restrict__ Wh2,
                       const float* __restrict__ bh2, float* __restrict__ Hio,
                       uint2* __restrict__ Hh, int N_) {
    constexpr int KF = KORD * HID;
    extern __shared__ float sm[];
    float* wsh = sm;                        // KF*32
    float* insh = sm + KF * 32;
    int tid = threadIdx.x;
    for (int i = tid; i < KF * 32; i += blockDim.x) wsh[i] = Wh2[i];
    __syncthreads();
    int wid = tid >> 5, lane = tid & 31;
    float4* st4 = ((float4*)insh) + wid * KF;
    float b2 = bh2[lane];
    for (int n0 = blockIdx.x * 8; n0 < N_; n0 += gridDim.x * 8) {
        int n = n0 + wid;
        if (n >= N_) break;
        float4 acc = gather_h(xh, n, lane);
        float4 t1v = ((const float4*)T1f)[n * 32 + lane];
        float dg = g_diag[n];
        acc.x = fmaf(dg, t1v.x, acc.x); acc.y = fmaf(dg, t1v.y, acc.y);
        acc.z = fmaf(dg, t1v.z, acc.z); acc.w = fmaf(dg, t1v.w, acc.w);
        float4 p = ((const float4*)T0)[n * 32 + lane];
        acc.x = 2.f * acc.x - p.x; acc.y = 2.f * acc.y - p.y;
        acc.z = 2.f * acc.z - p.z; acc.w = 2.f * acc.w - p.w;
        st4[lane] = p; st4[32 + lane] = t1v; st4[64 + lane] = acc;
        __syncwarp();
        float4 ah = make_float4(0.f, 0.f, 0.f, 0.f);
        const float* wg = wsh + lane;
#pragma unroll 4
        for (int i = 0; i < KF; i++) {
            float4 v = st4[i];
            float a = wg[i * 32];
            ah.x = fmaf(a, v.x, ah.x); ah.y = fmaf(a, v.y, ah.y);
            ah.z = fmaf(a, v.z, ah.z); ah.w = fmaf(a, v.w, ah.w);
        }
        float4 gx2 = ((const float4*)g_gx)[(n * 3 + 2) * 32 + lane];
        float4 Z = ((const float4*)g_Zb)[n * 32 + lane];
        float4 H = ((const float4*)Hio)[n * 32 + lane];
        float4 Hn;
        Hn.x = Z.x * H.x + (1.f - Z.x) * tanhf(gx2.x + ah.x + b2);
        Hn.y = Z.y * H.y + (1.f - Z.y) * tanhf(gx2.y + ah.y + b2);
        Hn.z = Z.z * H.z + (1.f - Z.z) * tanhf(gx2.z + ah.z + b2);
        Hn.w = Z.w * H.w + (1.f - Z.w) * tanhf(gx2.w + ah.w + b2);
        ((float4*)Hio)[n * 32 + lane] = Hn;
        Hh[n * 32 + lane] = pack4(Hn);
        __syncwarp();
    }
}

// fused hop2 + gx (layer0, F=8, fp32 path): T0 = X, T1f = X-basis hop1
__global__ void f_gx8_k(const float* __restrict__ T0, const float* __restrict__ T1f,
                        const float* __restrict__ Wx, const float* __restrict__ bx,
                        int N_) {
    constexpr int KF = KORD * FIN;   // 24
    extern __shared__ float sm[];
    float* wsh = sm;                        // 3*KF*32
    float* insh = sm + 3 * KF * 32;         // 8 warps * 96 floats
    int tid = threadIdx.x;
    for (int i = tid; i < 3 * KF * 32; i += blockDim.x) wsh[i] = Wx[i];
    __syncthreads();
    int wid = tid >> 5, lane = tid & 31;
    float* st = insh + wid * 96;
    float4* in4 = (float4*)st;
    float b0 = bx[lane], b1 = bx[32 + lane], b2 = bx[64 + lane];
    for (int n0 = blockIdx.x * 8; n0 < N_; n0 += gridDim.x * 8) {
        int n = n0 + wid;
        if (n >= N_) break;
        // hop2 gather (fp32 scalar payload)
        int o0 = g_off[n], o1 = g_off[n + 1];
        float acc = 0.f;
        for (int base = o0; base < o1; base += 32) {
            int idx = base + lane;
            int s = 0; float w = 0.f;
            if (idx < o1) {
                float2 e = g_edge[idx];
                s = __float_as_int(e.x); w = e.y;
            }
            int m = min(32, o1 - base);
            int j = 0;
            for (; j + 3 < m; j += 4) {
                int   s0 = __shfl_sync(FULLM, s, j);
                int   s1 = __shfl_sync(FULLM, s, j + 1);
                int   s2 = __shfl_sync(FULLM, s, j + 2);
                int   s3 = __shfl_sync(FULLM, s, j + 3);
                float w0 = __shfl_sync(FULLM, w, j);
                float w1 = __shfl_sync(FULLM, w, j + 1);
                float w2 = __shfl_sync(FULLM, w, j + 2);
                float w3 = __shfl_sync(FULLM, w, j + 3);
                acc = fmaf(w0, T1f[s0 * 32 + lane], acc);
                acc = fmaf(w1, T1f[s1 * 32 + lane], acc);
                acc = fmaf(w2, T1f[s2 * 32 + lane], acc);
                acc = fmaf(w3, T1f[s3 * 32 + lane], acc);
            }
            for (; j < m; j++) {
                int   sj = __shfl_sync(FULLM, s, j);
                float wj = __shfl_sync(FULLM, w, j);
                acc = fmaf(wj, T1f[sj * 32 + lane], acc);
            }
        }
        float t1 = T1f[n * 32 + lane];
        acc = fmaf(g_diag[n], t1, acc);
        float p = T0[n * 32 + lane];
        acc = 2.f * acc - p;
        st[lane] = p; st[32 + lane] = t1; st[64 + lane] = acc;
        __syncwarp();
        for (int g = 0; g < 3; g++) {
            float ax = 0.f, ay = 0.f, az = 0.f, aw = 0.f;
            const float* wg = wsh + g * KF * 32 + lane;
#pragma unroll
            for (int i = 0; i < KF; i++) {
                float w = wg[i * 32];
                float4 v = in4[i];
                ax = fmaf(w, v.x, ax); ay = fmaf(w, v.y, ay);
                az = fmaf(w, v.z, az); aw = fmaf(w, v.w, aw);
            }
            float bb = (g == 0) ? b0 : (g == 1) ? b1 : b2;
            ((float4*)g_gx)[(n * 3 + g) * 32 + lane] =
                make_float4(ax + bb, ay + bb, az + bb, aw + bb);
        }
        __syncwarp();
    }
}

// ---------------- standalone gate kernels (zr0 every step; t==0 zero paths) ----------------
__global__ void zr_k(const float* __restrict__ T0, const float* __restrict__ T1v,
                     const float* __restrict__ T2v, const float* __restrict__ Wh,
                     const float* __restrict__ bh, uint2* __restrict__ HRh, int N_) {
    constexpr int F = HID, KF = KORD * HID;
    extern __shared__ float sm[];
    float* wsh = sm;
    float* insh = sm + 2 * KF * 32;
    int tid = threadIdx.x;
    for (int i = tid; i < 2 * KF * 32; i += blockDim.x) wsh[i] = Wh[i];
    __syncthreads();
    int wid = tid >> 5, lane = tid & 31;
    float4* in4 = ((float4*)insh) + wid * KF;
    const float* Ts[3] = {T0, T1v, T2v};
    for (int n0 = blockIdx.x * 8; n0 < N_; n0 += gridDim.x * 8) {
        int n = n0 + wid;
        if (n >= N_) break;
        for (int k = 0; k < 3; k++)
            for (int i = lane; i < F; i += 32)
                in4[k * F + i] = ((const float4*)Ts[k])[n * F + i];
        __syncwarp();
        float4 az = make_float4(0.f, 0.f, 0.f, 0.f);
        float4 ar = make_float4(0.f, 0.f, 0.f, 0.f);
        const float* wz = wsh + lane;
        const float* wr = wsh + KF * 32 + lane;
#pragma unroll 4
        for (int i = 0; i < KF; i++) {
            float4 v = in4[i];
            float a = wz[i * 32];
            az.x = fmaf(a, v.x, az.x); az.y = fmaf(a, v.y, az.y);
            az.z = fmaf(a, v.z, az.z); az.w = fmaf(a, v.w, az.w);
            float b = wr[i * 32];
            ar.x = fmaf(b, v.x, ar.x); ar.y = fmaf(b, v.y, ar.y);
            ar.z = fmaf(b, v.z, ar.z); ar.w = fmaf(b, v.w, ar.w);
        }
        float4 gx0 = ((const float4*)g_gx)[(n * 3 + 0) * 32 + lane];
        float4 gx1 = ((const float4*)g_gx)[(n * 3 + 1) * 32 + lane];
        float bz = bh[lane], br = bh[32 + lane];
        float4 H = in4[lane];
        float4 Z, HR;
        Z.x = sigm(gx0.x + az.x + bz); Z.y = sigm(gx0.y + az.y + bz);
        Z.z = sigm(gx0.z + az.z + bz); Z.w = sigm(gx0.w + az.w + bz);
        HR.x = H.x * sigm(gx1.x + ar.x + br);
        HR.y = H.y * sigm(gx1.y + ar.y + br);
        HR.z = H.z * sigm(gx1.z + ar.z + br);
        HR.w = H.w * sigm(gx1.w + ar.w + br);
        ((float4*)g_Zb)[n * 32 + lane] = Z;
        ((float4*)g_HR)[n * 32 + lane] = HR;
        HRh[n * 32 + lane] = pack4(HR);
        __syncwarp();
    }
}

__global__ void gh_k(const float* __restrict__ T0, const float* __restrict__ T1v,
                     const float* __restrict__ T2v, const float* __restrict__ Wh2,
                     const float* __restrict__ bh2, float* __restrict__ Hio,
                     uint2* __restrict__ Hh, int N_) {
    constexpr int F = HID, KF = KORD * HID;
    extern __shared__ float sm[];
    float* wsh = sm;
    float* insh = sm + KF * 32;
    int tid = threadIdx.x;
    for (int i = tid; i < KF * 32; i += blockDim.x) wsh[i] = Wh2[i];
    __syncthreads();
    int wid = tid >> 5, lane = tid & 31;
    float4* in4 = ((float4*)insh) + wid * KF;
    const float* Ts[3] = {T0, T1v, T2v};
    for (int n0 = blockIdx.x * 8; n0 < N_; n0 += gridDim.x * 8) {
        int n = n0 + wid;
        if (n >= N_) break;
        for (int k = 0; k < 3; k++)
            for (int i = lane; i < F; i += 32)
                in4[k * F + i] = ((const float4*)Ts[k])[n * F + i];
        __syncwarp();
        float4 ah = make_float4(0.f, 0.f, 0.f, 0.f);
        const float* wg = wsh + lane;
#pragma unroll 4
        for (int i = 0; i < KF; i++) {
            float4 v = in4[i];
            float a = wg[i * 32];
            ah.x = fmaf(a, v.x, ah.x); ah.y = fmaf(a, v.y, ah.y);
            ah.z = fmaf(a, v.z, ah.z); ah.w = fmaf(a, v.w, ah.w);
        }
        float4 gx2 = ((const float4*)g_gx)[(n * 3 + 2) * 32 + lane];
        float b2 = bh2[lane];
        float4 Z = ((const float4*)g_Zb)[n * 32 + lane];
        float4 H = ((const float4*)Hio)[n * 32 + lane];
        float4 Hn;
        Hn.x = Z.x * H.x + (1.f - Z.x) * tanhf(gx2.x + ah.x + b2);
        Hn.y = Z.y * H.y + (1.f - Z.y) * tanhf(gx2.y + ah.y + b2);
        Hn.z = Z.z * H.z + (1.f - Z.z) * tanhf(gx2.z + ah.z + b2);
        Hn.w = Z.w * H.w + (1.f - Z.w) * tanhf(gx2.w + ah.w + b2);
        ((float4*)Hio)[n * 32 + lane] = Hn;
        Hh[n * 32 + lane] = pack4(Hn);
        __syncwarp();
    }
}

// ---------------- heads ----------------
__global__ void musig_k(const float* __restrict__ H2, const float* __restrict__ muW,
                        const float* __restrict__ mub, const float* __restrict__ sgW,
                        const float* __restrict__ sgb, float* __restrict__ out, int N_) {
    int tid = blockIdx.x * blockDim.x + threadIdx.x;
    if (tid >= N_ * BB) return;
    int b = tid & 3;
    int n = tid >> 2;
    float a0 = 0.f, a1 = 0.f, s0 = 0.f, s1 = 0.f;
#pragma unroll
    for (int i = 0; i < HID; i++) {
        float h = H2[(n * HID + i) * BB + b];
        a0 = fmaf(h, muW[i * 2 + 0], a0);
        a1 = fmaf(h, muW[i * 2 + 1], a1);
        s0 = fmaf(h, sgW[i * 2 + 0], s0);
        s1 = fmaf(h, sgW[i * 2 + 1], s1);
    }
    a0 += mub[0]; a1 += mub[1]; s0 += sgb[0]; s1 += sgb[1];
    out[((long long)b * N_ + n) * 2 + 0] = sigm(a0);
    out[((long long)b * N_ + n) * 2 + 1] = sigm(a1);
    float* so = out + (long long)BB * N_ * 2;
    so[((long long)b * N_ + n) * 2 + 0] = softplusf(s0);
    so[((long long)b * N_ + n) * 2 + 1] = softplusf(s1);
}

__global__ void sum_k(const float* __restrict__ H2, int N_) {
    int tid = threadIdx.x;
    int per = (N_ + gridDim.x - 1) / gridDim.x;
    int n0 = blockIdx.x * per;
    int n1 = min(n0 + per, N_);
    float acc = 0.f;
    for (int n = n0; n < n1; n++) acc += H2[n * 128 + tid];
    atomicAdd(&g_S[tid], acc);
}

__global__ void mix_k(float* __restrict__ out, int N_) {
    int lane = threadIdx.x & 31;
    int b = threadIdx.x >> 5;
    float v = g_S[lane * BB + b] / (float)N_;
    float m = v;
    for (int o = 16; o; o >>= 1) m = fmaxf(m, __shfl_xor_sync(FULLM, m, o));
    float e = expf(v - m);
    float s = e;
    for (int o = 16; o; o >>= 1) s += __shfl_xor_sync(FULLM, s, o);
    out[(long long)BB * N_ * 4 + b * HID + lane] = e / s;
}

// ---------------- launcher ----------------
extern "C" void kernel_launch(void* const* d_in, const int* in_sizes, int n_in,
                              void* d_out, int out_size) {
    const float* in_tensor = (const float*)d_in[0];
    const void*  ei  = d_in[1];
    const float* ew  = (const float*)d_in[2];
    const float* Wx0 = (const float*)d_in[3];
    const float* Wh0 = (const float*)d_in[4];
    const float* bx0 = (const float*)d_in[5];
    const float* bh0 = (const float*)d_in[6];
    const float* Wx1 = (const float*)d_in[7];
    const float* Wh1 = (const float*)d_in[8];
    const float* bx1 = (const float*)d_in[9];
    const float* bh1 = (const float*)d_in[10];
    const float* muW = (const float*)d_in[11];
    const float* mub = (const float*)d_in[12];
    const float* sgW = (const float*)d_in[13];
    const float* sgb = (const float*)d_in[14];
    float* out = (float*)d_out;

    int E  = in_sizes[1] / 2;
    int N_ = in_sizes[0] / (BB * TT * FIN);

    void *pdeg, *pcnt, *pcur, *pS, *pH1, *pH2, *pT1, *pT2, *pT1b, *pT2b, *pX, *pHR;
    void *pH1h, *pH2h, *pHRh, *pT1h;
    cudaGetSymbolAddress(&pdeg, g_deg);
    cudaGetSymbolAddress(&pcnt, g_cnt);
    cudaGetSymbolAddress(&pcur, g_cur);
    cudaGetSymbolAddress(&pS,   g_S);
    cudaGetSymbolAddress(&pH1,  g_H1);
    cudaGetSymbolAddress(&pH2,  g_H2);
    cudaGetSymbolAddress(&pT1,  g_T1);
    cudaGetSymbolAddress(&pT2,  g_T2);
    cudaGetSymbolAddress(&pT1b, g_T1b);
    cudaGetSymbolAddress(&pT2b, g_T2b);
    cudaGetSymbolAddress(&pX,   g_X);
    cudaGetSymbolAddress(&pHR,  g_HR);
    cudaGetSymbolAddress(&pH1h, g_H1h);
    cudaGetSymbolAddress(&pH2h, g_H2h);
    cudaGetSymbolAddress(&pHRh, g_HRh);
    cudaGetSymbolAddress(&pT1h, g_T1h);
    float *T1 = (float*)pT1, *T2 = (float*)pT2, *X = (float*)pX;
    float *T1b = (float*)pT1b, *T2b = (float*)pT2b;
    float *H1 = (float*)pH1, *H2 = (float*)pH2, *HR = (float*)pHR;
    uint2 *H1h = (uint2*)pH1h, *H2h = (uint2*)pH2h, *HRh = (uint2*)pHRh, *T1h = (uint2*)pT1h;

    const int smem_fgx8  = (3 * KORD * FIN * 32 + 8 * 96) * 4;
    const int smem_fgx32 = (3 * KORD * HID * 32 + 8 * KORD * HID * 4) * 4;
    const int smem_fzr   = (2 * KORD * HID * 32 + 8 * KORD * HID * 4) * 4;
    const int smem_fgh   = (1 * KORD * HID * 32 + 8 * KORD * HID * 4) * 4;
    cudaFuncSetAttribute((const void*)f_gx8_k,  cudaFuncAttributeMaxDynamicSharedMemorySize, 65536);
    cudaFuncSetAttribute((const void*)f_gx32_k, cudaFuncAttributeMaxDynamicSharedMemorySize, 65536);
    cudaFuncSetAttribute((const void*)f_zr_k,   cudaFuncAttributeMaxDynamicSharedMemorySize, 65536);
    cudaFuncSetAttribute((const void*)f_gh_k,   cudaFuncAttributeMaxDynamicSharedMemorySize, 65536);
    cudaFuncSetAttribute((const void*)zr_k,     cudaFuncAttributeMaxDynamicSharedMemorySize, 65536);
    cudaFuncSetAttribute((const void*)gh_k,     cudaFuncAttributeMaxDynamicSharedMemorySize, 65536);

    cudaMemsetAsync(pdeg, 0, (size_t)N_ * 4);
    cudaMemsetAsync(pcnt, 0, (size_t)N_ * 4);
    cudaMemsetAsync(pcur, 0, (size_t)N_ * 4);
    cudaMemsetAsync(pS,   0, 128 * 4);
    cudaMemsetAsync(pH1,  0, (size_t)N_ * 128 * 4);
    cudaMemsetAsync(pH2,  0, (size_t)N_ * 128 * 4);
    cudaMemsetAsync(pT1b, 0, (size_t)N_ * 128 * 4);
    cudaMemsetAsync(pT2b, 0, (size_t)N_ * 128 * 4);

    int ebl = (E + 255) / 256;
    int nb_sp = (N_ * 32 + 255) / 256;   // hop1: one warp per node
    int nb_g  = 592;                     // standalone gates
    int nb_f  = 1184;                    // fused hop2+gate grid
    int nzf   = (N_ * 32 + 255) / 256;
    const int WH = 2 * KORD * HID * HID;

    detect_k<<<1, 1>>>((const int*)ei, in_sizes[1]);
    edge_init_k<<<ebl, 256>>>(ei, ew, E);
    node_prep_k<<<(N_ + 255) / 256, 256>>>(N_);
    scan_k<<<1, 1024>>>(N_);
    fill_k<<<ebl, 256>>>(ew, E);

    for (int t = 0; t < TT; t++) {
        // ---- layer 0 (input F=8) ----
        xgather_k<<<(N_ * FIN * BB + 255) / 256, 256>>>(in_tensor, t, N_);
        spmm32_k<<<nb_sp, 256>>>(T1, X, N_);                       // X-basis hop1
        f_gx8_k<<<nb_f, 256, smem_fgx8>>>(X, T1, Wx0, bx0, N_);    // fused hop2 + gx0
        zr_k<<<nb_g, 256, smem_fzr>>>(H1, T1b, T2b, Wh0, bh0, HRh, N_);  // prev basis
        if (t == 0) {
            zero2_k<<<nzf, 256>>>(T1, T2, N_ * 32);                // basis(HR)==0
            gh_k<<<nb_g, 256, smem_fgh>>>(HR, T1, T2, Wh0 + WH, bh0 + 2 * HID, H1, H1h, N_);
        } else {
            spmmh_k<<<nb_sp, 256>>>(T1, T1h, HRh, N_);             // HR-basis hop1
            f_gh_k<<<nb_f, 256, smem_fgh>>>(HR, T1, T1h, Wh0 + WH, bh0 + 2 * HID, H1, H1h, N_);
        }

        // ---- layer 1 (input = H1, F=32) ----
        spmmh_k<<<nb_sp, 256>>>(T1b, T1h, H1h, N_);                // H1-basis hop1 (persisted)
        f_gx32_k<<<nb_f, 256, smem_fgx32>>>(H1, T1b, T1h, T2b, Wx1, bx1, N_);  // + T2b persist
        if (t == 0) {
            // basis(H2)==0 and basis(HR)==0: T1/T2 are still zero from layer-0 zero2_k
            zr_k<<<nb_g, 256, smem_fzr>>>(H2, T1, T2, Wh1, bh1, HRh, N_);
            gh_k<<<nb_g, 256, smem_fgh>>>(HR, T1, T2, Wh1 + WH, bh1 + 2 * HID, H2, H2h, N_);
        } else {
            spmmh_k<<<nb_sp, 256>>>(T1, T1h, H2h, N_);             // H2-basis hop1
            f_zr_k<<<nb_f, 256, smem_fzr>>>(H2, T1, T1h, Wh1, bh1, HRh, N_);
            spmmh_k<<<nb_sp, 256>>>(T1, T1h, HRh, N_);             // HR-basis hop1
            f_gh_k<<<nb_f, 256, smem_fgh>>>(HR, T1, T1h, Wh1 + WH, bh1 + 2 * HID, H2, H2h, N_);
        }
    }

    musig_k<<<(N_ * BB + 255) / 256, 256>>>(H2, muW, mub, sgW, sgb, out, N_);
    sum_k<<<256, 128>>>(H2, N_);
    mix_k<<<1, 128>>>(out, N_);
}